// round 1
// baseline (speedup 1.0000x reference)
#include <cuda_runtime.h>
#include <math.h>

#define BATCH 4
#define SEQ   2048
#define NH    16
#define DHEAD 64
#define DMODEL 1024

// Scratch (allocation-free rule: __device__ globals)
__device__ float g_q[(size_t)BATCH*NH*SEQ*DHEAD];
__device__ float g_k[(size_t)BATCH*NH*SEQ*DHEAD];
__device__ float g_v[(size_t)BATCH*NH*SEQ*DHEAD];
__device__ float g_att[(size_t)BATCH*SEQ*DMODEL];

// ---------------------------------------------------------------------------
// QKV projection: for each (proj, head, batch, s-tile) compute 64x64 tile of
// out[s][d] = sum_m x[s][m] * W[h][m][d] + bias[h][d]
// Output layout: ((b*NH+h)*SEQ + s)*64 + d
// ---------------------------------------------------------------------------
__global__ __launch_bounds__(256) void qkv_kernel(
    const float* __restrict__ x,
    const float* __restrict__ Qw, const float* __restrict__ Qb,
    const float* __restrict__ Kw, const float* __restrict__ Kb,
    const float* __restrict__ Vw, const float* __restrict__ Vb)
{
    __shared__ float As[16][68];   // [k][row] (transposed A tile)
    __shared__ float Bs[16][68];   // [k][col]

    const int st = blockIdx.x & 31;        // s-tile (SEQ/64 = 32)
    const int b  = blockIdx.x >> 5;
    const int proj = blockIdx.y >> 4;
    const int h    = blockIdx.y & 15;

    const float* W; const float* bias; float* out;
    if (proj == 0)      { W = Qw; bias = Qb; out = g_q; }
    else if (proj == 1) { W = Kw; bias = Kb; out = g_k; }
    else                { W = Vw; bias = Vb; out = g_v; }

    const float* Ap = x + ((size_t)b*SEQ + (size_t)st*64) * DMODEL;
    const float* Bp = W + (size_t)h * DMODEL * DHEAD;
    float* outp = out + (((size_t)(b*NH + h))*SEQ + (size_t)st*64) * DHEAD;

    const int t    = threadIdx.x;
    const int arow = t >> 2;          // 0..63
    const int akg  = t & 3;           // 0..3 (k-group of 4)
    const int brow = t >> 4;          // 0..15
    const int bc4  = (t & 15) * 4;    // 0..60
    const int tr   = t >> 4;          // 0..15 -> rows tr*4..tr*4+3
    const int tc   = t & 15;          // 0..15 -> cols tc*4..tc*4+3

    float c[4][4] = {};

    for (int k0 = 0; k0 < DMODEL; k0 += 16) {
        float4 av = *(const float4*)(Ap + (size_t)arow*DMODEL + k0 + akg*4);
        As[akg*4+0][arow] = av.x;
        As[akg*4+1][arow] = av.y;
        As[akg*4+2][arow] = av.z;
        As[akg*4+3][arow] = av.w;
        *(float4*)&Bs[brow][bc4] =
            *(const float4*)(Bp + (size_t)(k0 + brow)*DHEAD + bc4);
        __syncthreads();

        #pragma unroll
        for (int kk = 0; kk < 16; kk++) {
            float4 a4 = *(float4*)&As[kk][tr*4];
            float4 b4 = *(float4*)&Bs[kk][tc*4];
            float a[4] = {a4.x, a4.y, a4.z, a4.w};
            float bb[4] = {b4.x, b4.y, b4.z, b4.w};
            #pragma unroll
            for (int i = 0; i < 4; i++)
                #pragma unroll
                for (int j = 0; j < 4; j++)
                    c[i][j] += a[i] * bb[j];
        }
        __syncthreads();
    }

    #pragma unroll
    for (int i = 0; i < 4; i++) {
        float4 o;
        o.x = c[i][0] + bias[h*DHEAD + tc*4 + 0];
        o.y = c[i][1] + bias[h*DHEAD + tc*4 + 1];
        o.z = c[i][2] + bias[h*DHEAD + tc*4 + 2];
        o.w = c[i][3] + bias[h*DHEAD + tc*4 + 3];
        *(float4*)(outp + (size_t)(tr*4 + i)*DHEAD + tc*4) = o;
    }
}

// ---------------------------------------------------------------------------
// Causal flash attention, fp32. One block = (q-tile of 64 rows, one (b,h)).
// Writes g_att[(b*SEQ+s)*1024 + h*64 + d]  (== attention output, pre O-proj)
// ---------------------------------------------------------------------------
__global__ __launch_bounds__(256) void attn_kernel()
{
    extern __shared__ float sm[];
    float (*Qs)[68] = (float(*)[68])(sm);
    float (*KT)[68] = (float(*)[68])(sm + 64*68);      // [k][c] (K transposed)
    float (*Vs)[68] = (float(*)[68])(sm + 2*64*68);    // [c][d]
    float (*Ps)[68] = (float(*)[68])(sm + 3*64*68);    // [r][c]

    const int qt = blockIdx.x;
    const int bh = blockIdx.y;
    const int b  = bh >> 4;
    const int h  = bh & 15;

    const size_t base = (size_t)bh * SEQ * DHEAD;
    const float* Qp = g_q + base + (size_t)qt*64*DHEAD;
    const float* Kp = g_k + base;
    const float* Vp = g_v + base;

    const int t  = threadIdx.x;
    const int r0 = (t >> 4) * 4;   // rows r0..r0+3
    const int c0 = (t & 15) * 4;   // cols c0..c0+3

    const float scale = 0.125f;  // 1/sqrt(64)

    // Load Q tile, pre-scaled
    #pragma unroll
    for (int u = 0; u < 4; u++) {
        int idx  = t + u*256;
        int row  = idx >> 4;
        int col4 = (idx & 15) * 4;
        float4 v = *(const float4*)(Qp + (size_t)row*DHEAD + col4);
        v.x *= scale; v.y *= scale; v.z *= scale; v.w *= scale;
        *(float4*)&Qs[row][col4] = v;
    }

    float m_i[4] = {-1e30f, -1e30f, -1e30f, -1e30f};
    float l_i[4] = {0.f, 0.f, 0.f, 0.f};
    float O[4][4] = {};

    for (int kt = 0; kt <= qt; kt++) {
        __syncthreads();   // K/V/P buffers free (prev PV done), Q ready (kt=0)

        const float* Kt = Kp + (size_t)kt*64*DHEAD;
        const float* Vt = Vp + (size_t)kt*64*DHEAD;
        #pragma unroll
        for (int u = 0; u < 4; u++) {
            int idx  = t + u*256;
            int row  = idx >> 4;
            int col4 = (idx & 15) * 4;
            float4 kv = *(const float4*)(Kt + (size_t)row*DHEAD + col4);
            KT[col4+0][row] = kv.x;
            KT[col4+1][row] = kv.y;
            KT[col4+2][row] = kv.z;
            KT[col4+3][row] = kv.w;
            *(float4*)&Vs[row][col4] =
                *(const float4*)(Vt + (size_t)row*DHEAD + col4);
        }
        __syncthreads();

        // Scores: s[i][j] = Q[r0+i] . K[c0+j]  (Q pre-scaled)
        float s[4][4] = {};
        #pragma unroll
        for (int k4 = 0; k4 < 64; k4 += 4) {
            float qreg[4][4];
            #pragma unroll
            for (int i = 0; i < 4; i++) {
                float4 qv = *(float4*)&Qs[r0+i][k4];
                qreg[i][0]=qv.x; qreg[i][1]=qv.y; qreg[i][2]=qv.z; qreg[i][3]=qv.w;
            }
            #pragma unroll
            for (int u = 0; u < 4; u++) {
                float4 kv = *(float4*)&KT[k4+u][c0];
                float kr[4] = {kv.x, kv.y, kv.z, kv.w};
                #pragma unroll
                for (int i = 0; i < 4; i++)
                    #pragma unroll
                    for (int j = 0; j < 4; j++)
                        s[i][j] += qreg[i][u] * kr[j];
            }
        }

        // Causal mask (only diagonal tile); matches reference's -1e5 mask
        if (kt == qt) {
            #pragma unroll
            for (int i = 0; i < 4; i++)
                #pragma unroll
                for (int j = 0; j < 4; j++)
                    if (c0 + j > r0 + i) s[i][j] = -100000.0f;
        }

        // Online softmax update
        #pragma unroll
        for (int i = 0; i < 4; i++) {
            float v = fmaxf(fmaxf(s[i][0], s[i][1]), fmaxf(s[i][2], s[i][3]));
            v = fmaxf(v, __shfl_xor_sync(0xffffffffu, v, 1));
            v = fmaxf(v, __shfl_xor_sync(0xffffffffu, v, 2));
            v = fmaxf(v, __shfl_xor_sync(0xffffffffu, v, 4));
            v = fmaxf(v, __shfl_xor_sync(0xffffffffu, v, 8));
            float mnew = fmaxf(m_i[i], v);
            float fac  = __expf(m_i[i] - mnew);
            m_i[i] = mnew;

            float p0 = __expf(s[i][0] - mnew);
            float p1 = __expf(s[i][1] - mnew);
            float p2 = __expf(s[i][2] - mnew);
            float p3 = __expf(s[i][3] - mnew);
            *(float4*)&Ps[r0+i][c0] = make_float4(p0, p1, p2, p3);
            float su = p0 + p1 + p2 + p3;
            su += __shfl_xor_sync(0xffffffffu, su, 1);
            su += __shfl_xor_sync(0xffffffffu, su, 2);
            su += __shfl_xor_sync(0xffffffffu, su, 4);
            su += __shfl_xor_sync(0xffffffffu, su, 8);
            l_i[i] = l_i[i]*fac + su;
            #pragma unroll
            for (int j = 0; j < 4; j++) O[i][j] *= fac;
        }
        __syncthreads();   // Ps complete

        // O += P * V
        #pragma unroll
        for (int c4 = 0; c4 < 64; c4 += 4) {
            float preg[4][4];
            #pragma unroll
            for (int i = 0; i < 4; i++) {
                float4 pv = *(float4*)&Ps[r0+i][c4];
                preg[i][0]=pv.x; preg[i][1]=pv.y; preg[i][2]=pv.z; preg[i][3]=pv.w;
            }
            #pragma unroll
            for (int u = 0; u < 4; u++) {
                float4 vv = *(float4*)&Vs[c4+u][c0];
                float vr[4] = {vv.x, vv.y, vv.z, vv.w};
                #pragma unroll
                for (int i = 0; i < 4; i++)
                    #pragma unroll
                    for (int j = 0; j < 4; j++)
                        O[i][j] += preg[i][u] * vr[j];
            }
        }
    }

    // Normalize + write to g_att[(b*SEQ + s)*1024 + h*64 + d]
    float* outp = g_att + ((size_t)b*SEQ + (size_t)qt*64) * DMODEL + h*DHEAD;
    #pragma unroll
    for (int i = 0; i < 4; i++) {
        float inv = 1.0f / l_i[i];
        float4 o = make_float4(O[i][0]*inv, O[i][1]*inv, O[i][2]*inv, O[i][3]*inv);
        *(float4*)(outp + (size_t)(r0 + i)*DMODEL + c0) = o;
    }
}

// ---------------------------------------------------------------------------
// Output projection: out[8192,1024] = g_att[8192,1024] @ O_w[1024,1024] + O_b
// (O_w (H, D_head, D_model) flattens exactly to row-major (1024, 1024))
// ---------------------------------------------------------------------------
__global__ __launch_bounds__(256) void oproj_kernel(
    const float* __restrict__ Ow, const float* __restrict__ Ob,
    float* __restrict__ out)
{
    __shared__ float As[16][68];
    __shared__ float Bs[16][68];

    const int rt = blockIdx.x;     // 0..127  (row tile)
    const int nt = blockIdx.y;     // 0..15   (col tile)

    const float* Ap = g_att + (size_t)rt*64*DMODEL;
    const float* Bp = Ow + nt*64;
    float* outp = out + (size_t)rt*64*DMODEL + nt*64;

    const int t    = threadIdx.x;
    const int arow = t >> 2;
    const int akg  = t & 3;
    const int brow = t >> 4;
    const int bc4  = (t & 15) * 4;
    const int tr   = t >> 4;
    const int tc   = t & 15;

    float c[4][4] = {};

    for (int k0 = 0; k0 < DMODEL; k0 += 16) {
        float4 av = *(const float4*)(Ap + (size_t)arow*DMODEL + k0 + akg*4);
        As[akg*4+0][arow] = av.x;
        As[akg*4+1][arow] = av.y;
        As[akg*4+2][arow] = av.z;
        As[akg*4+3][arow] = av.w;
        *(float4*)&Bs[brow][bc4] =
            *(const float4*)(Bp + (size_t)(k0 + brow)*DMODEL + bc4);
        __syncthreads();

        #pragma unroll
        for (int kk = 0; kk < 16; kk++) {
            float4 a4 = *(float4*)&As[kk][tr*4];
            float4 b4 = *(float4*)&Bs[kk][tc*4];
            float a[4] = {a4.x, a4.y, a4.z, a4.w};
            float bb[4] = {b4.x, b4.y, b4.z, b4.w};
            #pragma unroll
            for (int i = 0; i < 4; i++)
                #pragma unroll
                for (int j = 0; j < 4; j++)
                    c[i][j] += a[i] * bb[j];
        }
        __syncthreads();
    }

    #pragma unroll
    for (int i = 0; i < 4; i++) {
        float4 o;
        o.x = c[i][0] + Ob[nt*64 + tc*4 + 0];
        o.y = c[i][1] + Ob[nt*64 + tc*4 + 1];
        o.z = c[i][2] + Ob[nt*64 + tc*4 + 2];
        o.w = c[i][3] + Ob[nt*64 + tc*4 + 3];
        *(float4*)(outp + (size_t)(tr*4 + i)*DMODEL + tc*4) = o;
    }
}

extern "C" void kernel_launch(void* const* d_in, const int* in_sizes, int n_in,
                              void* d_out, int out_size)
{
    const float* x  = (const float*)d_in[0];
    const float* Qw = (const float*)d_in[1];
    const float* Qb = (const float*)d_in[2];
    const float* Kw = (const float*)d_in[3];
    const float* Kb = (const float*)d_in[4];
    const float* Vw = (const float*)d_in[5];
    const float* Vb = (const float*)d_in[6];
    const float* Ow = (const float*)d_in[7];
    const float* Ob = (const float*)d_in[8];
    float* out = (float*)d_out;

    // QKV projection: 128 (s-tile x batch) x 48 (proj x head)
    qkv_kernel<<<dim3(128, 48), 256>>>(x, Qw, Qb, Kw, Kb, Vw, Vb);

    // Flash attention: 32 q-tiles x 64 (b,h)
    const int smem = 4 * 64 * 68 * sizeof(float);  // 69632 B
    cudaFuncSetAttribute(attn_kernel,
                         cudaFuncAttributeMaxDynamicSharedMemorySize, smem);
    attn_kernel<<<dim3(32, 64), 256, smem>>>();

    // Output projection: 128 row tiles x 16 col tiles
    oproj_kernel<<<dim3(128, 16), 256>>>(Ow, Ob, out);
}

// round 3
// speedup vs baseline: 4.1788x; 4.1788x over previous
#include <cuda_runtime.h>
#include <math.h>

#define BATCH 4
#define SEQ   2048
#define NH    16
#define DHEAD 64
#define DMODEL 1024

// Scratch (allocation-free rule: __device__ globals)
__device__ float g_q[(size_t)BATCH*NH*SEQ*DHEAD];
__device__ float g_k[(size_t)BATCH*NH*SEQ*DHEAD];
__device__ float g_v[(size_t)BATCH*NH*SEQ*DHEAD];
__device__ float g_att[(size_t)BATCH*SEQ*DMODEL];

__device__ __forceinline__ unsigned f2tf(float f){
    unsigned u;
    asm("cvt.rna.tf32.f32 %0, %1;" : "=r"(u) : "f"(f));
    return u;
}

__device__ __forceinline__ void mma_tf32(float* d, const unsigned* a, const unsigned* b){
    asm volatile(
        "mma.sync.aligned.m16n8k8.row.col.f32.tf32.tf32.f32 "
        "{%0,%1,%2,%3},{%4,%5,%6,%7},{%8,%9},{%0,%1,%2,%3};\n"
        : "+f"(d[0]), "+f"(d[1]), "+f"(d[2]), "+f"(d[3])
        : "r"(a[0]), "r"(a[1]), "r"(a[2]), "r"(a[3]), "r"(b[0]), "r"(b[1]));
}

// ---------------------------------------------------------------------------
// Shared tf32 GEMM core: C[128 x 64] tile = A[128 x K] * B[K x 64] + bias
// 256 threads, 8 warps in 4(M) x 2(N) grid, warp tile 32x32, BK=16.
// ---------------------------------------------------------------------------
__device__ __forceinline__ void gemm_compute_step(
    const unsigned (*As)[136], const unsigned (*Bs)[72],
    float acc[2][4][4], int wm, int wn, int g, int tig)
{
    #pragma unroll
    for (int ks = 0; ks < 2; ks++) {
        const int kk = ks*8 + tig;
        unsigned afr[2][4], bfr[4][2];
        #pragma unroll
        for (int mt = 0; mt < 2; mt++) {
            const int m0 = wm*32 + mt*16 + g;
            afr[mt][0] = As[kk  ][m0];
            afr[mt][1] = As[kk  ][m0+8];
            afr[mt][2] = As[kk+4][m0];
            afr[mt][3] = As[kk+4][m0+8];
        }
        #pragma unroll
        for (int nt = 0; nt < 4; nt++) {
            const int n0 = wn*32 + nt*8 + g;
            bfr[nt][0] = Bs[kk  ][n0];
            bfr[nt][1] = Bs[kk+4][n0];
        }
        #pragma unroll
        for (int mt = 0; mt < 2; mt++)
            #pragma unroll
            for (int nt = 0; nt < 4; nt++)
                mma_tf32(acc[mt][nt], afr[mt], bfr[nt]);
    }
}

__device__ __forceinline__ void gemm128x64(
    const float* __restrict__ A, int lda,
    const float* __restrict__ B, int ldb,
    const float* __restrict__ bias,
    float* __restrict__ C, int ldc, int K)
{
    __shared__ unsigned As[16][136];   // [k][m], pitch 136 -> conflict-free frag reads
    __shared__ unsigned Bs[16][72];    // [k][n], pitch 72

    const int t    = threadIdx.x;
    const int lane = t & 31, warp = t >> 5;
    const int wm = warp >> 1, wn = warp & 1;
    const int g  = lane >> 2, tig = lane & 3;

    const int arow = t >> 2,  acol = (t & 3) * 4;
    const int brow = t >> 4,  bcol = (t & 15) * 4;

    float acc[2][4][4];
    #pragma unroll
    for (int i = 0; i < 2; i++)
        #pragma unroll
        for (int j = 0; j < 4; j++)
            #pragma unroll
            for (int c = 0; c < 4; c++) acc[i][j][c] = 0.f;

    float4 av0 = *(const float4*)(A + (size_t)arow*lda + acol);
    float4 av1 = *(const float4*)(A + (size_t)(arow+64)*lda + acol);
    float4 bv  = *(const float4*)(B + (size_t)brow*ldb + bcol);

    // stage tile 0
    As[acol+0][arow]    = f2tf(av0.x); As[acol+1][arow]    = f2tf(av0.y);
    As[acol+2][arow]    = f2tf(av0.z); As[acol+3][arow]    = f2tf(av0.w);
    As[acol+0][arow+64] = f2tf(av1.x); As[acol+1][arow+64] = f2tf(av1.y);
    As[acol+2][arow+64] = f2tf(av1.z); As[acol+3][arow+64] = f2tf(av1.w);
    {
        uint4 bu = make_uint4(f2tf(bv.x), f2tf(bv.y), f2tf(bv.z), f2tf(bv.w));
        *(uint4*)&Bs[brow][bcol] = bu;
    }
    __syncthreads();

    const int iters = K / 16;
    for (int it = 1; it < iters; it++) {
        av0 = *(const float4*)(A + (size_t)arow*lda + it*16 + acol);
        av1 = *(const float4*)(A + (size_t)(arow+64)*lda + it*16 + acol);
        bv  = *(const float4*)(B + (size_t)(it*16+brow)*ldb + bcol);

        gemm_compute_step(As, Bs, acc, wm, wn, g, tig);

        __syncthreads();
        As[acol+0][arow]    = f2tf(av0.x); As[acol+1][arow]    = f2tf(av0.y);
        As[acol+2][arow]    = f2tf(av0.z); As[acol+3][arow]    = f2tf(av0.w);
        As[acol+0][arow+64] = f2tf(av1.x); As[acol+1][arow+64] = f2tf(av1.y);
        As[acol+2][arow+64] = f2tf(av1.z); As[acol+3][arow+64] = f2tf(av1.w);
        uint4 bu = make_uint4(f2tf(bv.x), f2tf(bv.y), f2tf(bv.z), f2tf(bv.w));
        *(uint4*)&Bs[brow][bcol] = bu;
        __syncthreads();
    }
    gemm_compute_step(As, Bs, acc, wm, wn, g, tig);

    // epilogue
    #pragma unroll
    for (int mt = 0; mt < 2; mt++) {
        #pragma unroll
        for (int nt = 0; nt < 4; nt++) {
            const int row = wm*32 + mt*16 + g;
            const int col = wn*32 + nt*8 + 2*tig;
            const float b0 = bias[col], b1 = bias[col+1];
            *(float2*)(C + (size_t)row*ldc + col) =
                make_float2(acc[mt][nt][0] + b0, acc[mt][nt][1] + b1);
            *(float2*)(C + (size_t)(row+8)*ldc + col) =
                make_float2(acc[mt][nt][2] + b0, acc[mt][nt][3] + b1);
        }
    }
}

// ---------------------------------------------------------------------------
// QKV projection
// ---------------------------------------------------------------------------
__global__ __launch_bounds__(256) void qkv_kernel(
    const float* __restrict__ x,
    const float* __restrict__ Qw, const float* __restrict__ Qb,
    const float* __restrict__ Kw, const float* __restrict__ Kb,
    const float* __restrict__ Vw, const float* __restrict__ Vb)
{
    const int proj = blockIdx.y >> 4;
    const int h    = blockIdx.y & 15;

    const float* W; const float* bias; float* out;
    if (proj == 0)      { W = Qw; bias = Qb; out = g_q; }
    else if (proj == 1) { W = Kw; bias = Kb; out = g_k; }
    else                { W = Vw; bias = Vb; out = g_v; }

    const int rbase = blockIdx.x * 128;        // global row in 0..8191
    const int b     = rbase / SEQ;
    const int srow  = rbase % SEQ;

    gemm128x64(x + (size_t)rbase * DMODEL, DMODEL,
               W + (size_t)h * DMODEL * DHEAD, DHEAD,
               bias + h * DHEAD,
               out + (((size_t)(b*NH + h))*SEQ + srow) * DHEAD, DHEAD,
               DMODEL);
}

// ---------------------------------------------------------------------------
// Output projection
// ---------------------------------------------------------------------------
__global__ __launch_bounds__(256) void oproj_kernel(
    const float* __restrict__ Ow, const float* __restrict__ Ob,
    float* __restrict__ out)
{
    const int rbase = blockIdx.x * 128;
    const int nbase = blockIdx.y * 64;
    gemm128x64(g_att + (size_t)rbase * DMODEL, DMODEL,
               Ow + nbase, DMODEL,
               Ob + nbase,
               out + (size_t)rbase * DMODEL + nbase, DMODEL,
               DMODEL);
}

// ---------------------------------------------------------------------------
// Causal flash attention, tf32 tensor cores. Block = (64 q rows, one (b,h)).
// 8 warps: warp grid 4(M=16) x 2(N=32).
// ---------------------------------------------------------------------------
__global__ __launch_bounds__(256) void attn_kernel()
{
    extern __shared__ unsigned smu[];
    unsigned* Qs = smu;              // [64][68] tf32, pre-scaled Q
    unsigned* Ks = Qs + 64*68;       // [64][68] tf32
    unsigned* Vs = Ks + 64*68;       // [64][72] tf32
    unsigned* Ps = Vs + 64*72;       // [64][68] tf32
    float* redM  = (float*)(Ps + 64*68);   // [2][64]
    float* redS  = redM + 128;             // [2][64]

    const int qt = (int)(gridDim.x - 1 - blockIdx.x);  // big tiles first
    const int bh = blockIdx.y;
    const int b  = bh >> 4;
    const int h  = bh & 15;

    const size_t base = (size_t)bh * SEQ * DHEAD;
    const float* Qp = g_q + base + (size_t)qt*64*DHEAD;
    const float* Kp = g_k + base;
    const float* Vp = g_v + base;

    const int t = threadIdx.x, lane = t & 31, warp = t >> 5;
    const int wm = warp >> 1, wn = warp & 1;
    const int g  = lane >> 2, tig = lane & 3;
    const int r_lo = wm*16 + g, r_hi = r_lo + 8;

    // Load Q tile, pre-scaled by 1/sqrt(64)
    #pragma unroll
    for (int u = 0; u < 4; u++) {
        int idx = t + u*256;
        int row = idx >> 4, col = (idx & 15) * 4;
        float4 v = *(const float4*)(Qp + (size_t)row*DHEAD + col);
        Qs[row*68 + col + 0] = f2tf(v.x * 0.125f);
        Qs[row*68 + col + 1] = f2tf(v.y * 0.125f);
        Qs[row*68 + col + 2] = f2tf(v.z * 0.125f);
        Qs[row*68 + col + 3] = f2tf(v.w * 0.125f);
    }

    float m0 = -1e30f, m1 = -1e30f, l0 = 0.f, l1 = 0.f;
    float oacc[4][4];
    #pragma unroll
    for (int i = 0; i < 4; i++)
        #pragma unroll
        for (int j = 0; j < 4; j++) oacc[i][j] = 0.f;

    for (int kt = 0; kt <= qt; kt++) {
        __syncthreads();  // prev PV done; Q staged (first iter)

        const float* Kt = Kp + (size_t)kt*64*DHEAD;
        const float* Vt = Vp + (size_t)kt*64*DHEAD;
        #pragma unroll
        for (int u = 0; u < 4; u++) {
            int idx = t + u*256;
            int row = idx >> 4, col = (idx & 15) * 4;
            float4 kv = *(const float4*)(Kt + (size_t)row*DHEAD + col);
            Ks[row*68 + col + 0] = f2tf(kv.x);
            Ks[row*68 + col + 1] = f2tf(kv.y);
            Ks[row*68 + col + 2] = f2tf(kv.z);
            Ks[row*68 + col + 3] = f2tf(kv.w);
            float4 vv = *(const float4*)(Vt + (size_t)row*DHEAD + col);
            Vs[row*72 + col + 0] = f2tf(vv.x);
            Vs[row*72 + col + 1] = f2tf(vv.y);
            Vs[row*72 + col + 2] = f2tf(vv.z);
            Vs[row*72 + col + 3] = f2tf(vv.w);
        }
        __syncthreads();

        // S = Q * K^T  (m=64, n=64, k=64)
        float sacc[4][4];
        #pragma unroll
        for (int i = 0; i < 4; i++)
            #pragma unroll
            for (int j = 0; j < 4; j++) sacc[i][j] = 0.f;

        #pragma unroll
        for (int ks = 0; ks < 8; ks++) {
            const int kk = ks*8 + tig;
            unsigned a[4] = { Qs[r_lo*68 + kk], Qs[r_hi*68 + kk],
                              Qs[r_lo*68 + kk + 4], Qs[r_hi*68 + kk + 4] };
            #pragma unroll
            for (int nt = 0; nt < 4; nt++) {
                const int n0 = wn*32 + nt*8 + g;
                unsigned bfr[2] = { Ks[n0*68 + kk], Ks[n0*68 + kk + 4] };
                mma_tf32(sacc[nt], a, bfr);
            }
        }

        // causal mask on diagonal tile (matches reference's -1e5)
        if (kt == qt) {
            #pragma unroll
            for (int nt = 0; nt < 4; nt++) {
                const int c = wn*32 + nt*8 + 2*tig;
                if (c     > r_lo) sacc[nt][0] = -100000.0f;
                if (c + 1 > r_lo) sacc[nt][1] = -100000.0f;
                if (c     > r_hi) sacc[nt][2] = -100000.0f;
                if (c + 1 > r_hi) sacc[nt][3] = -100000.0f;
            }
        }

        // row max: warp-partial via shfl, cross-warp via smem
        float pm0 = -1e30f, pm1 = -1e30f;
        #pragma unroll
        for (int nt = 0; nt < 4; nt++) {
            pm0 = fmaxf(pm0, fmaxf(sacc[nt][0], sacc[nt][1]));
            pm1 = fmaxf(pm1, fmaxf(sacc[nt][2], sacc[nt][3]));
        }
        pm0 = fmaxf(pm0, __shfl_xor_sync(0xffffffffu, pm0, 1));
        pm0 = fmaxf(pm0, __shfl_xor_sync(0xffffffffu, pm0, 2));
        pm1 = fmaxf(pm1, __shfl_xor_sync(0xffffffffu, pm1, 1));
        pm1 = fmaxf(pm1, __shfl_xor_sync(0xffffffffu, pm1, 2));
        if (tig == 0) { redM[wn*64 + r_lo] = pm0; redM[wn*64 + r_hi] = pm1; }
        __syncthreads();
        pm0 = fmaxf(pm0, redM[(wn^1)*64 + r_lo]);
        pm1 = fmaxf(pm1, redM[(wn^1)*64 + r_hi]);

        const float mn0 = fmaxf(m0, pm0), mn1 = fmaxf(m1, pm1);
        const float f0 = __expf(m0 - mn0), f1 = __expf(m1 - mn1);
        m0 = mn0; m1 = mn1;

        float ps0 = 0.f, ps1 = 0.f;
        #pragma unroll
        for (int nt = 0; nt < 4; nt++) {
            const float p0 = __expf(sacc[nt][0] - mn0);
            const float p1 = __expf(sacc[nt][1] - mn0);
            const float p2 = __expf(sacc[nt][2] - mn1);
            const float p3 = __expf(sacc[nt][3] - mn1);
            ps0 += p0 + p1; ps1 += p2 + p3;
            const int c = wn*32 + nt*8 + 2*tig;
            *(uint2*)&Ps[r_lo*68 + c] = make_uint2(f2tf(p0), f2tf(p1));
            *(uint2*)&Ps[r_hi*68 + c] = make_uint2(f2tf(p2), f2tf(p3));
            oacc[nt][0] *= f0; oacc[nt][1] *= f0;
            oacc[nt][2] *= f1; oacc[nt][3] *= f1;
        }
        ps0 += __shfl_xor_sync(0xffffffffu, ps0, 1);
        ps0 += __shfl_xor_sync(0xffffffffu, ps0, 2);
        ps1 += __shfl_xor_sync(0xffffffffu, ps1, 1);
        ps1 += __shfl_xor_sync(0xffffffffu, ps1, 2);
        if (tig == 0) { redS[wn*64 + r_lo] = ps0; redS[wn*64 + r_hi] = ps1; }
        __syncthreads();  // also guarantees Ps complete before PV mma
        ps0 += redS[(wn^1)*64 + r_lo];
        ps1 += redS[(wn^1)*64 + r_hi];
        l0 = l0*f0 + ps0;
        l1 = l1*f1 + ps1;

        // O += P * V  (m=64, n=64(dhead), k=64(keys))
        #pragma unroll
        for (int ks = 0; ks < 8; ks++) {
            const int kk = ks*8 + tig;
            unsigned a[4] = { Ps[r_lo*68 + kk], Ps[r_hi*68 + kk],
                              Ps[r_lo*68 + kk + 4], Ps[r_hi*68 + kk + 4] };
            #pragma unroll
            for (int nt = 0; nt < 4; nt++) {
                const int n0 = wn*32 + nt*8 + g;
                unsigned bfr[2] = { Vs[kk*72 + n0], Vs[(kk+4)*72 + n0] };
                mma_tf32(oacc[nt], a, bfr);
            }
        }
    }

    // normalize + write g_att[(b*SEQ + s)*1024 + h*64 + d]
    const float inv0 = 1.0f / l0, inv1 = 1.0f / l1;
    float* outp = g_att + ((size_t)b*SEQ + (size_t)qt*64)*DMODEL + h*DHEAD;
    #pragma unroll
    for (int nt = 0; nt < 4; nt++) {
        const int c = wn*32 + nt*8 + 2*tig;
        *(float2*)(outp + (size_t)r_lo*DMODEL + c) =
            make_float2(oacc[nt][0]*inv0, oacc[nt][1]*inv0);
        *(float2*)(outp + (size_t)r_hi*DMODEL + c) =
            make_float2(oacc[nt][2]*inv1, oacc[nt][3]*inv1);
    }
}

extern "C" void kernel_launch(void* const* d_in, const int* in_sizes, int n_in,
                              void* d_out, int out_size)
{
    const float* x  = (const float*)d_in[0];
    const float* Qw = (const float*)d_in[1];
    const float* Qb = (const float*)d_in[2];
    const float* Kw = (const float*)d_in[3];
    const float* Kb = (const float*)d_in[4];
    const float* Vw = (const float*)d_in[5];
    const float* Vb = (const float*)d_in[6];
    const float* Ow = (const float*)d_in[7];
    const float* Ob = (const float*)d_in[8];
    float* out = (float*)d_out;

    // QKV projection: 64 m-tiles x 48 (proj,head)
    qkv_kernel<<<dim3(64, 48), 256>>>(x, Qw, Qb, Kw, Kb, Vw, Vb);

    // Flash attention: 32 q-tiles x 64 (b,h)
    const int smem = (64*68*3 + 64*72) * 4 + 2*128*4;  // 71680 B
    cudaFuncSetAttribute(attn_kernel,
                         cudaFuncAttributeMaxDynamicSharedMemorySize, smem);
    attn_kernel<<<dim3(32, 64), 256, smem>>>();

    // Output projection: 64 m-tiles x 16 n-tiles
    oproj_kernel<<<dim3(64, 16), 256>>>(Ow, Ob, out);
}